// round 3
// baseline (speedup 1.0000x reference)
#include <cuda_runtime.h>
#include <cstring>

// Closed-form: dynamics are affine, so 8 RK4 substeps collapse to one affine
// map X_final = R8*X0 + T*b (coefficients built on host in double).
//
// R3: persistent grid + double-buffered smem software pipeline. Each block
// grid-strides over 256-env tiles; the next tile's global loads are issued
// into registers before computing/storing the current tile, keeping DRAM
// reads in flight across the barriers and interleaving reads with writes.

struct Coef {
    float a01, a02, a12, a22;
    float u0, u1, u2;
    float d0, d1, d2;
};

#define THREADS 256
#define ENVS    256
#define XV4     576   // ENVS*9/4
#define UV4     192   // ENVS*3/4

__global__ void __launch_bounds__(THREADS)
pointmass_kernel(const float4* __restrict__ x0v,
                 const float4* __restrict__ uv,
                 float4* __restrict__ outv,
                 Coef C, int NT)
{
    __shared__ float4 sx[2][XV4];
    __shared__ float4 su[2][UV4];

    const int tid    = threadIdx.x;
    const int stride = gridDim.x;
    int t = blockIdx.x;
    if (t >= NT) return;

    const bool p64  = (tid < 64);
    const bool p192 = (tid < 192);

    // ---- prologue: load tile t -> regs -> smem[0]
    float4 xr0, xr1, xtail, ur;
    {
        const size_t xb = (size_t)t * XV4;
        const size_t ub = (size_t)t * UV4;
        xr0 = x0v[xb + tid];
        xr1 = x0v[xb + tid + 256];
        if (p64)  xtail = x0v[xb + tid + 512];
        if (p192) ur    = uv[ub + tid];
    }
    int cur = 0;
    sx[cur][tid]       = xr0;
    sx[cur][tid + 256] = xr1;
    if (p64)  sx[cur][tid + 512] = xtail;
    if (p192) su[cur][tid]       = ur;
    __syncthreads();

    while (true) {
        const int  tn       = t + stride;
        const bool has_next = (tn < NT);

        // ---- issue next tile's global loads (in flight during compute+store)
        if (has_next) {
            const size_t xb = (size_t)tn * XV4;
            const size_t ub = (size_t)tn * UV4;
            xr0 = x0v[xb + tid];
            xr1 = x0v[xb + tid + 256];
            if (p64)  xtail = x0v[xb + tid + 512];
            if (p192) ur    = uv[ub + tid];
        }

        // ---- compute tile t in place (one env per thread; stride-9 smem,
        // gcd(9,32)=1 -> conflict-free; cells private to this thread)
        {
            float* xp       = reinterpret_cast<float*>(sx[cur]) + tid * 9;
            const float* up = reinterpret_cast<float*>(su[cur]) + tid * 3;

            #pragma unroll
            for (int f = 0; f < 3; f++) {
                float p = xp[f];
                float v = xp[f + 3];
                float a = xp[f + 6];
                float u = up[f];

                float np = fmaf(C.a01, v, fmaf(C.a02, a, fmaf(C.u0, u, p)));
                float nv = fmaf(C.a12, a, fmaf(C.u1, u, v));
                float na = fmaf(C.a22, a, C.u2 * u);
                if (f == 2) { np += C.d0; nv += C.d1; na += C.d2; }

                xp[f]     = np;
                xp[f + 3] = nv;
                xp[f + 6] = na;
            }
        }
        __syncthreads();

        // ---- store tile t (coalesced) and stage next tile into other buffer
        const int nxt = cur ^ 1;
        {
            const size_t xb = (size_t)t * XV4;
            outv[xb + tid]       = sx[cur][tid];
            outv[xb + tid + 256] = sx[cur][tid + 256];
            if (p64) outv[xb + tid + 512] = sx[cur][tid + 512];
        }
        if (has_next) {
            sx[nxt][tid]       = xr0;
            sx[nxt][tid + 256] = xr1;
            if (p64)  sx[nxt][tid + 512] = xtail;
            if (p192) su[nxt][tid]       = ur;
        } else {
            break;
        }
        __syncthreads();

        cur = nxt;
        t   = tn;
    }
}

// ---------------- host-side 3x3 double matrix helpers ----------------

static void m_mul(const double A[3][3], const double B[3][3], double C[3][3]) {
    double T[3][3];
    for (int i = 0; i < 3; i++)
        for (int j = 0; j < 3; j++) {
            double s = 0.0;
            for (int k = 0; k < 3; k++) s += A[i][k] * B[k][j];
            T[i][j] = s;
        }
    std::memcpy(C, T, sizeof(T));
}

static void m_addscaled(double A[3][3], const double B[3][3], double s) {
    for (int i = 0; i < 3; i++)
        for (int j = 0; j < 3; j++) A[i][j] += s * B[i][j];
}

extern "C" void kernel_launch(void* const* d_in, const int* in_sizes, int n_in,
                              void* d_out, int out_size)
{
    const float4* x0v = (const float4*)d_in[0];
    const float4* uv  = (const float4*)d_in[1];
    float4* outv      = (float4*)d_out;

    const int n_envs = in_sizes[0] / 9;   // 2097152

    const double DT = 0.02;
    const double h  = DT / 8.0;
    const double c  = 0.5 / DT;
    const double g  = 9.81;

    double I[3][3]  = {{1,0,0},{0,1,0},{0,0,1}};
    double hA[3][3] = {{0,h,0},{0,0,h},{0,0,-h*c}};

    double H2[3][3], H3[3][3], H4[3][3];
    m_mul(hA, hA, H2);
    m_mul(H2, hA, H3);
    m_mul(H3, hA, H4);

    double R[3][3];
    std::memcpy(R, I, sizeof(R));
    m_addscaled(R, hA, 1.0);
    m_addscaled(R, H2, 1.0/2.0);
    m_addscaled(R, H3, 1.0/6.0);
    m_addscaled(R, H4, 1.0/24.0);

    double S[3][3];
    std::memcpy(S, I, sizeof(S));
    m_addscaled(S, hA, 1.0/2.0);
    m_addscaled(S, H2, 1.0/6.0);
    m_addscaled(S, H3, 1.0/24.0);
    for (int i = 0; i < 3; i++)
        for (int j = 0; j < 3; j++) S[i][j] *= h;

    double P[3][3], Rk[3][3];
    std::memcpy(P, I, sizeof(P));
    std::memcpy(Rk, I, sizeof(Rk));
    for (int k = 1; k < 8; k++) {
        m_mul(Rk, R, Rk);
        m_addscaled(P, Rk, 1.0);
    }
    double R8[3][3];
    m_mul(Rk, R, R8);

    double T[3][3];
    m_mul(P, S, T);

    Coef C;
    C.a01 = (float)R8[0][1];
    C.a02 = (float)R8[0][2];
    C.a12 = (float)R8[1][2];
    C.a22 = (float)R8[2][2];
    C.u0  = (float)(c * T[0][2]);
    C.u1  = (float)(c * T[1][2]);
    C.u2  = (float)(c * T[2][2]);
    C.d0  = (float)(g * T[0][1]);
    C.d1  = (float)(g * T[1][1]);
    C.d2  = (float)(g * T[2][1]);

    const int NT     = n_envs / ENVS;                 // 8192 tiles
    int blocks       = 148 * 8;                       // persistent grid
    if (blocks > NT) blocks = NT;

    pointmass_kernel<<<blocks, THREADS>>>(x0v, uv, outv, C, NT);
}

// round 4
// speedup vs baseline: 1.1528x; 1.1528x over previous
#include <cuda_runtime.h>
#include <cstdint>
#include <cstring>

// Closed-form: dynamics are affine, so 8 RK4 substeps collapse to one affine
// map X_final = R8*X0 + T*b (coefficients built on host in double).
//
// R4: cp.async.bulk (TMA path) for ALL global<->shared movement. 3 smem
// buffers, depth-2 prefetch, mbarrier-paced. Registers/L1 only touched for
// the 21-float affine map per env. Non-persistent grid (2048 blocks x 4
// tiles) to keep hardware wave balancing.

struct Coef {
    float a01, a02, a12, a22;
    float u0, u1, u2;
    float d0, d1, d2;
};

#define THREADS 256
#define ENVS    256          // envs per tile
#define XB      9216         // 256*9*4 bytes
#define UB      3072         // 256*3*4 bytes
#define TPB     4            // tiles per block
#define NBUF    3

// ---------------- PTX helpers ----------------

__device__ __forceinline__ uint32_t smem_u32(const void* p) {
    uint32_t a;
    asm("{ .reg .u64 t; cvta.to.shared.u64 t, %1; cvt.u32.u64 %0, t; }"
        : "=r"(a) : "l"(p));
    return a;
}

__device__ __forceinline__ void mbar_init(uint32_t mbar, uint32_t count) {
    asm volatile("mbarrier.init.shared.b64 [%0], %1;" :: "r"(mbar), "r"(count) : "memory");
}

__device__ __forceinline__ void mbar_expect_tx(uint32_t mbar, uint32_t bytes) {
    asm volatile("mbarrier.arrive.expect_tx.shared.b64 _, [%0], %1;"
                 :: "r"(mbar), "r"(bytes) : "memory");
}

__device__ __forceinline__ void mbar_wait(uint32_t mbar, uint32_t parity) {
    uint32_t done;
    asm volatile(
        "{\n\t.reg .pred p;\n\t"
        "mbarrier.try_wait.parity.acquire.cta.shared::cta.b64 p, [%1], %2;\n\t"
        "selp.b32 %0, 1, 0, p;\n\t}"
        : "=r"(done) : "r"(mbar), "r"(parity) : "memory");
    if (!done) {
        asm volatile(
            "{\n\t.reg .pred P1;\n\t"
            "W_%=:\n\t"
            "mbarrier.try_wait.parity.acquire.cta.shared::cta.b64 P1, [%0], %1, 0x989680;\n\t"
            "@P1 bra.uni D_%=;\n\t"
            "bra.uni W_%=;\n\t"
            "D_%=:\n\t}"
            :: "r"(mbar), "r"(parity) : "memory");
    }
}

__device__ __forceinline__ void bulk_g2s(uint32_t dst, const void* src,
                                         uint32_t bytes, uint32_t mbar) {
    asm volatile(
        "cp.async.bulk.shared::cta.global.mbarrier::complete_tx::bytes [%0], [%1], %2, [%3];"
        :: "r"(dst), "l"(src), "r"(bytes), "r"(mbar) : "memory");
}

__device__ __forceinline__ void bulk_s2g(void* dst, uint32_t src, uint32_t bytes) {
    asm volatile(
        "cp.async.bulk.global.shared::cta.bulk_group [%0], [%1], %2;"
        :: "l"(dst), "r"(src), "r"(bytes) : "memory");
}

__device__ __forceinline__ void bulk_commit() {
    asm volatile("cp.async.bulk.commit_group;" ::: "memory");
}

template <int N>
__device__ __forceinline__ void bulk_wait_read() {
    asm volatile("cp.async.bulk.wait_group.read %0;" :: "n"(N) : "memory");
}

template <int N>
__device__ __forceinline__ void bulk_wait() {
    asm volatile("cp.async.bulk.wait_group %0;" :: "n"(N) : "memory");
}

// ---------------- kernel ----------------

__global__ void __launch_bounds__(THREADS)
pointmass_kernel(const char* __restrict__ gx,
                 const char* __restrict__ gu,
                 char* __restrict__ gout,
                 Coef C)
{
    __shared__ __align__(128) char sx[NBUF][XB];
    __shared__ __align__(128) char su[NBUF][UB];
    __shared__ __align__(8)   uint64_t mbar_mem[NBUF];

    const int tid = threadIdx.x;

    uint32_t sxa[NBUF], sua[NBUF], mb[NBUF];
    #pragma unroll
    for (int b = 0; b < NBUF; b++) {
        sxa[b] = smem_u32(sx[b]);
        sua[b] = smem_u32(su[b]);
        mb[b]  = smem_u32(&mbar_mem[b]);
    }

    if (tid == 0) {
        #pragma unroll
        for (int b = 0; b < NBUF; b++) mbar_init(mb[b], 1);
    }
    __syncthreads();

    const long tile0 = (long)blockIdx.x * TPB;

    // Prologue: prefetch tiles 0 and 1 (depth 2).
    if (tid == 0) {
        #pragma unroll
        for (int k = 0; k < 2; k++) {
            mbar_expect_tx(mb[k], XB + UB);
            bulk_g2s(sxa[k], gx + (tile0 + k) * XB, XB, mb[k]);
            bulk_g2s(sua[k], gu + (tile0 + k) * UB, UB, mb[k]);
        }
    }

    #pragma unroll
    for (int i = 0; i < TPB; i++) {
        const int b  = i % NBUF;
        const int ph = (i / NBUF) & 1;

        mbar_wait(mb[b], ph);   // acquire: TMA-written smem visible

        // ---- affine map, one env per thread (stride-9/3 smem: conflict-free)
        {
            float* xp       = reinterpret_cast<float*>(sx[b]) + tid * 9;
            const float* up = reinterpret_cast<float*>(su[b]) + tid * 3;

            #pragma unroll
            for (int f = 0; f < 3; f++) {
                float p = xp[f];
                float v = xp[f + 3];
                float a = xp[f + 6];
                float u = up[f];

                float np = fmaf(C.a01, v, fmaf(C.a02, a, fmaf(C.u0, u, p)));
                float nv = fmaf(C.a12, a, fmaf(C.u1, u, v));
                float na = fmaf(C.a22, a, C.u2 * u);
                if (f == 2) { np += C.d0; nv += C.d1; na += C.d2; }

                xp[f]     = np;
                xp[f + 3] = nv;
                xp[f + 6] = na;
            }
        }

        // order generic smem writes before async-proxy (TMA) read
        asm volatile("fence.proxy.async.shared::cta;" ::: "memory");
        __syncthreads();

        if (tid == 0) {
            bulk_s2g(gout + (tile0 + i) * XB, sxa[b], XB);
            bulk_commit();

            const int nxt = i + 2;
            if (nxt < TPB) {
                // Reusing buffer (i+2)%3, whose previous store was committed
                // at iter i-1. Outstanding groups: {i-1, i}; keep <=1 so the
                // oldest (i-1) has finished READING its smem source.
                bulk_wait_read<1>();
                const int bn = nxt % NBUF;
                mbar_expect_tx(mb[bn], XB + UB);
                bulk_g2s(sxa[bn], gx + (tile0 + nxt) * XB, XB, mb[bn]);
                bulk_g2s(sua[bn], gu + (tile0 + nxt) * UB, UB, mb[bn]);
            }
        }
        // No extra barrier: next iteration's mbar_wait gates the consumers.
    }

    // Drain pending bulk stores before kernel exit.
    if (tid == 0) bulk_wait<0>();
}

// ---------------- host-side 3x3 double matrix helpers ----------------

static void m_mul(const double A[3][3], const double B[3][3], double C[3][3]) {
    double T[3][3];
    for (int i = 0; i < 3; i++)
        for (int j = 0; j < 3; j++) {
            double s = 0.0;
            for (int k = 0; k < 3; k++) s += A[i][k] * B[k][j];
            T[i][j] = s;
        }
    std::memcpy(C, T, sizeof(T));
}

static void m_addscaled(double A[3][3], const double B[3][3], double s) {
    for (int i = 0; i < 3; i++)
        for (int j = 0; j < 3; j++) A[i][j] += s * B[i][j];
}

extern "C" void kernel_launch(void* const* d_in, const int* in_sizes, int n_in,
                              void* d_out, int out_size)
{
    const char* gx = (const char*)d_in[0];
    const char* gu = (const char*)d_in[1];
    char* gout     = (char*)d_out;

    const int n_envs = in_sizes[0] / 9;   // 2097152

    const double DT = 0.02;
    const double h  = DT / 8.0;
    const double c  = 0.5 / DT;
    const double g  = 9.81;

    double I[3][3]  = {{1,0,0},{0,1,0},{0,0,1}};
    double hA[3][3] = {{0,h,0},{0,0,h},{0,0,-h*c}};

    double H2[3][3], H3[3][3], H4[3][3];
    m_mul(hA, hA, H2);
    m_mul(H2, hA, H3);
    m_mul(H3, hA, H4);

    double R[3][3];
    std::memcpy(R, I, sizeof(R));
    m_addscaled(R, hA, 1.0);
    m_addscaled(R, H2, 1.0/2.0);
    m_addscaled(R, H3, 1.0/6.0);
    m_addscaled(R, H4, 1.0/24.0);

    double S[3][3];
    std::memcpy(S, I, sizeof(S));
    m_addscaled(S, hA, 1.0/2.0);
    m_addscaled(S, H2, 1.0/6.0);
    m_addscaled(S, H3, 1.0/24.0);
    for (int i = 0; i < 3; i++)
        for (int j = 0; j < 3; j++) S[i][j] *= h;

    double P[3][3], Rk[3][3];
    std::memcpy(P, I, sizeof(P));
    std::memcpy(Rk, I, sizeof(Rk));
    for (int k = 1; k < 8; k++) {
        m_mul(Rk, R, Rk);
        m_addscaled(P, Rk, 1.0);
    }
    double R8[3][3];
    m_mul(Rk, R, R8);

    double T[3][3];
    m_mul(P, S, T);

    Coef C;
    C.a01 = (float)R8[0][1];
    C.a02 = (float)R8[0][2];
    C.a12 = (float)R8[1][2];
    C.a22 = (float)R8[2][2];
    C.u0  = (float)(c * T[0][2]);
    C.u1  = (float)(c * T[1][2]);
    C.u2  = (float)(c * T[2][2]);
    C.d0  = (float)(g * T[0][1]);
    C.d1  = (float)(g * T[1][1]);
    C.d2  = (float)(g * T[2][1]);

    const int n_tiles = n_envs / ENVS;       // 8192
    const int blocks  = n_tiles / TPB;       // 2048, exact

    pointmass_kernel<<<blocks, THREADS>>>(gx, gu, gout, C);
}